// round 9
// baseline (speedup 1.0000x reference)
#include <cuda_runtime.h>
#include <math.h>

#define NB   4
#define NL   2048
#define ND   512
#define NH   8
#define NDK  64
#define NM   (NB*NL)   /* 8192 */

// Scratch (static __device__ arrays — allocation-free per harness rules)
__device__ float g_Q[NM*ND];    // (B,H,L,dk)
__device__ float g_K[NM*ND];    // (B,H,L,dk)
__device__ float g_V[NM*ND];    // (B,H,L,dk)
__device__ float g_att[NM*ND];  // (B,L,D)

// ---------------------------------------------------------------------------
// TF32 / cp.async helpers
// ---------------------------------------------------------------------------
__device__ __forceinline__ unsigned f2tf(float f) {
    unsigned u;
    asm("cvt.rna.tf32.f32 %0, %1;" : "=r"(u) : "f"(f));
    return u;
}

__device__ __forceinline__ void cpa16(float* sptr, const float* gptr) {
    unsigned s = (unsigned)__cvta_generic_to_shared(sptr);
    asm volatile("cp.async.cg.shared.global [%0], [%1], 16;" :: "r"(s), "l"(gptr));
}
__device__ __forceinline__ void cpa_commit() {
    asm volatile("cp.async.commit_group;" ::: "memory");
}
__device__ __forceinline__ void cpa_wait1() {
    asm volatile("cp.async.wait_group 1;" ::: "memory");
}
__device__ __forceinline__ void cpa_wait0() {
    asm volatile("cp.async.wait_group 0;" ::: "memory");
}

// D(16x8) += A(16x8) * B(8x8), tf32 inputs, fp32 accumulate.
// Lane mapping (g = lane>>2, t = lane&3):
//  A: a0=(g,t) a1=(g+8,t) a2=(g,t+4) a3=(g+8,t+4)   [row, k]
//  B: b0=(t,g) b1=(t+4,g)                            [k, n]
//  D: c0=(g,2t) c1=(g,2t+1) c2=(g+8,2t) c3=(g+8,2t+1)
__device__ __forceinline__ void mma8(float* d, const unsigned* a, const unsigned* b) {
    asm volatile("mma.sync.aligned.m16n8k8.row.col.f32.tf32.tf32.f32 "
                 "{%0,%1,%2,%3}, {%4,%5,%6,%7}, {%8,%9}, {%0,%1,%2,%3};"
                 : "+f"(d[0]), "+f"(d[1]), "+f"(d[2]), "+f"(d[3])
                 : "r"(a[0]), "r"(a[1]), "r"(a[2]), "r"(a[3]),
                   "r"(b[0]), "r"(b[1]));
}

// ---------------------------------------------------------------------------
// GEMM (tensor, cp.async double-buffered): Y = X @ W^T.
// X: (NM,512), W: (512,512), row-major fp32. Block tile (MT*64)m x 64n,
// K-chunk 32, 8 warps in 4(m) x 2(n), warp tile (MT*16) x 32.
// Smem holds raw fp32; tf32 conversion (cvt.rna) at fragment-load time.
// mode 0: Y[m*512+n]; mode 1: (B,H,L,dk) scatter, h = blockIdx.x.
// ---------------------------------------------------------------------------
#define XS_ST 36
#define WS_ST 36

template<int MT>
__device__ __forceinline__
void gemm_body(const float* __restrict__ X, const float* __restrict__ W,
               float* __restrict__ Y, int mode)
{
    constexpr int BM = MT * 64;
    extern __shared__ float smem[];
    float* Xs0 = smem;                       // 2 x BM*XS_ST
    float* Ws0 = smem + 2 * BM * XS_ST;      // 2 x 64*WS_ST

    const int tid  = threadIdx.x;
    const int w    = tid >> 5, lane = tid & 31;
    const int g    = lane >> 2, t = lane & 3;
    const int wm   = w & 3, wn = w >> 2;
    const int m0   = blockIdx.y * BM, n0 = blockIdx.x * 64;

    float acc[MT][4][4];
    #pragma unroll
    for (int mt = 0; mt < MT; mt++)
        #pragma unroll
        for (int nt = 0; nt < 4; nt++)
            #pragma unroll
            for (int i = 0; i < 4; i++) acc[mt][nt][i] = 0.f;

    // async stage of one K-chunk into buffer `buf`
    auto stage = [&](int k0, int buf) {
        float* Xs = Xs0 + buf * BM * XS_ST;
        float* Ws = Ws0 + buf * 64 * WS_ST;
        #pragma unroll
        for (int i = 0; i < MT * 2; i++) {           // BM*8 16B-chunks / 256 thr
            int idx = tid + 256 * i;
            int r = idx >> 3, c = (idx & 7) * 4;
            cpa16(&Xs[r * XS_ST + c], &X[(size_t)(m0 + r) * 512 + k0 + c]);
        }
        #pragma unroll
        for (int i = 0; i < 2; i++) {                // 512 chunks / 256 thr
            int idx = tid + 256 * i;
            int r = idx >> 3, c = (idx & 7) * 4;
            cpa16(&Ws[r * WS_ST + c], &W[(size_t)(n0 + r) * 512 + k0 + c]);
        }
        cpa_commit();
    };

    stage(0, 0);
    for (int kc = 0; kc < 16; kc++) {
        if (kc + 1 < 16) { stage((kc + 1) * 32, (kc + 1) & 1); cpa_wait1(); }
        else             { cpa_wait0(); }
        __syncthreads();

        const float* Xs = Xs0 + (kc & 1) * BM * XS_ST;
        const float* Ws = Ws0 + (kc & 1) * 64 * WS_ST;

        #pragma unroll
        for (int ks = 0; ks < 4; ks++) {
            unsigned a[MT][4], bb[4][2];
            #pragma unroll
            for (int mt = 0; mt < MT; mt++) {
                const float* p = &Xs[(wm * (MT * 16) + mt * 16 + g) * XS_ST + ks * 8 + t];
                a[mt][0] = f2tf(p[0]);
                a[mt][1] = f2tf(p[8 * XS_ST]);
                a[mt][2] = f2tf(p[4]);
                a[mt][3] = f2tf(p[8 * XS_ST + 4]);
            }
            #pragma unroll
            for (int nt = 0; nt < 4; nt++) {
                const float* p = &Ws[(wn * 32 + nt * 8 + g) * WS_ST + ks * 8 + t];
                bb[nt][0] = f2tf(p[0]);
                bb[nt][1] = f2tf(p[4]);
            }
            #pragma unroll
            for (int mt = 0; mt < MT; mt++)
                #pragma unroll
                for (int nt = 0; nt < 4; nt++)
                    mma8(acc[mt][nt], a[mt], bb[nt]);
        }
        __syncthreads();
    }

    // Epilogue
    #pragma unroll
    for (int mt = 0; mt < MT; mt++) {
        int row = m0 + wm * (MT * 16) + mt * 16 + g;
        #pragma unroll
        for (int nt = 0; nt < 4; nt++) {
            int off = wn * 32 + nt * 8 + 2 * t;      // 0..63 within n-block
            float2 v0 = make_float2(acc[mt][nt][0], acc[mt][nt][1]);
            float2 v1 = make_float2(acc[mt][nt][2], acc[mt][nt][3]);
            if (mode == 0) {
                float* p = &Y[(size_t)row * 512 + n0 + off];
                *(float2*)p = v0;
                *(float2*)(p + (size_t)8 * 512) = v1;
            } else {
                int b = row >> 11, l = row & 2047, h = blockIdx.x;
                size_t base = ((size_t)((b * 8 + h) * 2048 + l)) * 64 + off;
                *(float2*)&Y[base] = v0;
                *(float2*)&Y[base + (size_t)8 * 64] = v1;
            }
        }
    }
}

#define SMEM_GEMM4 ((2 * 256 * XS_ST + 2 * 64 * WS_ST) * 4)   /* 92160 B */
#define SMEM_GEMM2 ((2 * 128 * XS_ST + 2 * 64 * WS_ST) * 4)   /* 55296 B */

// Fused Q/K/V projection: gridDim.z = 3 selects the weight + destination.
__global__ __launch_bounds__(256)
void gemm_qkv(const float* __restrict__ X,
              const float* __restrict__ Wq, const float* __restrict__ Wk,
              const float* __restrict__ Wv,
              float* __restrict__ Qp, float* __restrict__ Kp, float* __restrict__ Vp)
{
    const float* W = (blockIdx.z == 0) ? Wq : (blockIdx.z == 1) ? Wk : Wv;
    float*       Y = (blockIdx.z == 0) ? Qp : (blockIdx.z == 1) ? Kp : Vp;
    gemm_body<4>(X, W, Y, 1);
}

__global__ __launch_bounds__(256)
void gemm_out(const float* __restrict__ X, const float* __restrict__ W,
              float* __restrict__ Y)
{
    gemm_body<2>(X, W, Y, 0);
}

// ---------------------------------------------------------------------------
// Wave attention (tensor, cp.async double-buffered K/V): 128 q-rows per
// block, 4 warps (32 rows each as 2 m-tiles), stream 64-key tiles;
// S=QK^T and O+=PV via tf32 mma; online softmax fp32.
// P never touches smem: S D-fragments are permuted to PV A-fragments with
// warp shuffles (col t <- lane 4g+(t>>1) comp t&1; col t+4 <- lane +2).
// Smem floats: Ks[2][64*68], Vs[2][64*72], wave[2048] = 79872 B -> 2 blk/SM.
// ---------------------------------------------------------------------------
#define KS_ST 68
#define VS_ST 72
#define SM_VS   (2 * 64 * KS_ST)
#define SM_WAVE (SM_VS + 2 * 64 * VS_ST)
#define SMEM_ATTN ((SM_WAVE + 2048) * 4)

__global__ __launch_bounds__(128, 2)
void wave_attn_tc(const float* __restrict__ wfreq, const float* __restrict__ wphase)
{
    extern __shared__ float sm[];
    float* Ks0 = sm;
    float* Vs0 = sm + SM_VS;
    float* Wv  = sm + SM_WAVE;

    const int tid = threadIdx.x;
    const int w   = tid >> 5, lane = tid & 31;
    const int g   = lane >> 2, t = lane & 3;
    const int bh  = blockIdx.y, b = bh >> 3, h = bh & 7;
    const int q0  = blockIdx.x * 128;

    const float* Qg = g_Q + ((size_t)bh * NL + q0) * NDK;
    const float* Kg = g_K + (size_t)bh * NL * NDK;
    const float* Vg = g_V + (size_t)bh * NL * NDK;

    // async stage of K/V tile kt into buffer `buf` (raw fp32)
    auto stage_kv = [&](int kt, int buf) {
        float* Ksb = Ks0 + buf * 64 * KS_ST;
        float* Vsb = Vs0 + buf * 64 * VS_ST;
        #pragma unroll
        for (int i = 0; i < 8; i++) {
            int idx = tid + 128 * i;
            int r = idx >> 4, c = (idx & 15) * 4;
            const float* gk = &Kg[(size_t)(kt * 64 + r) * 64 + c];
            const float* gv = &Vg[(size_t)(kt * 64 + r) * 64 + c];
            cpa16(&Ksb[r * KS_ST + c], gk);
            cpa16(&Vsb[r * VS_ST + c], gv);
        }
        cpa_commit();
    };

    stage_kv(0, 0);   // tile 0 in flight while we do wave table + Q fragments

    // Wave table (once per block)
    {
        const float f = wfreq[h], ph = wphase[h];
        const float TWO_PI = 6.28318530717958647692f;
        for (int j = tid; j < NL; j += 128)
            Wv[j] = cosf(TWO_PI * f * (float)j + ph);
    }

    // Q A-fragments straight from gmem (scaled by dk^-1/2, one-time)
    unsigned Qa[2][8][4];
    #pragma unroll
    for (int mt = 0; mt < 2; mt++)
        #pragma unroll
        for (int ks = 0; ks < 8; ks++) {
            const float* qp = &Qg[(w * 32 + mt * 16 + g) * 64 + ks * 8 + t];
            Qa[mt][ks][0] = f2tf(qp[0]            * 0.125f);
            Qa[mt][ks][1] = f2tf(qp[8 * 64]       * 0.125f);
            Qa[mt][ks][2] = f2tf(qp[4]            * 0.125f);
            Qa[mt][ks][3] = f2tf(qp[8 * 64 + 4]   * 0.125f);
        }

    float Oc[2][8][4];
    #pragma unroll
    for (int mt = 0; mt < 2; mt++)
        #pragma unroll
        for (int nt = 0; nt < 8; nt++)
            #pragma unroll
            for (int i = 0; i < 4; i++) Oc[mt][nt][i] = 0.f;
    float mA[2] = {-1e30f, -1e30f}, mB[2] = {-1e30f, -1e30f};
    float lA[2] = {0.f, 0.f},       lB[2] = {0.f, 0.f};

    const int srcA = (lane & 28) | (t >> 1);   // 4g + t/2
    const int srcB = srcA | 2;                 // 4g + t/2 + 2
    const bool odd = (t & 1);

    for (int kt = 0; kt < 32; kt++) {
        if (kt + 1 < 32) { stage_kv(kt + 1, (kt + 1) & 1); cpa_wait1(); }
        else             { cpa_wait0(); }
        __syncthreads();

        const float* Ksb = Ks0 + (kt & 1) * 64 * KS_ST;
        const float* Vsb = Vs0 + (kt & 1) * 64 * VS_ST;

        // S = Q @ K^T : both m-tiles share each B-fragment load (tf32 at read)
        float Sc[2][8][4];
        #pragma unroll
        for (int mt = 0; mt < 2; mt++)
            #pragma unroll
            for (int nt = 0; nt < 8; nt++)
                #pragma unroll
                for (int i = 0; i < 4; i++) Sc[mt][nt][i] = 0.f;
        #pragma unroll
        for (int ks = 0; ks < 8; ks++) {
            #pragma unroll
            for (int nt = 0; nt < 8; nt++) {
                unsigned bb[2];
                const float* p = &Ksb[(nt * 8 + g) * KS_ST + ks * 8 + t];
                bb[0] = f2tf(p[0]);
                bb[1] = f2tf(p[4]);
                mma8(Sc[0][nt], Qa[0][ks], bb);
                mma8(Sc[1][nt], Qa[1][ks], bb);
            }
        }

        // Wave modulation + online softmax per m-tile; Sc -> exp probs in place
        #pragma unroll
        for (int mt = 0; mt < 2; mt++) {
            float nmA = mA[mt], nmB = mB[mt];
            #pragma unroll
            for (int nt = 0; nt < 8; nt++) {
                int col = kt * 64 + nt * 8 + 2 * t;
                float w0 = Wv[col], w1 = Wv[col + 1];
                Sc[mt][nt][0] *= w0; Sc[mt][nt][1] *= w1;
                Sc[mt][nt][2] *= w0; Sc[mt][nt][3] *= w1;
                nmA = fmaxf(nmA, fmaxf(Sc[mt][nt][0], Sc[mt][nt][1]));
                nmB = fmaxf(nmB, fmaxf(Sc[mt][nt][2], Sc[mt][nt][3]));
            }
            nmA = fmaxf(nmA, __shfl_xor_sync(0xffffffffu, nmA, 1));
            nmB = fmaxf(nmB, __shfl_xor_sync(0xffffffffu, nmB, 1));
            nmA = fmaxf(nmA, __shfl_xor_sync(0xffffffffu, nmA, 2));
            nmB = fmaxf(nmB, __shfl_xor_sync(0xffffffffu, nmB, 2));

            float scA = __expf(mA[mt] - nmA), scB = __expf(mB[mt] - nmB);
            mA[mt] = nmA; mB[mt] = nmB;

            float psA = 0.f, psB = 0.f;
            #pragma unroll
            for (int nt = 0; nt < 8; nt++) {
                float p0 = __expf(Sc[mt][nt][0] - nmA);
                float p1 = __expf(Sc[mt][nt][1] - nmA);
                float p2 = __expf(Sc[mt][nt][2] - nmB);
                float p3 = __expf(Sc[mt][nt][3] - nmB);
                psA += p0 + p1; psB += p2 + p3;
                Sc[mt][nt][0] = p0; Sc[mt][nt][1] = p1;
                Sc[mt][nt][2] = p2; Sc[mt][nt][3] = p3;
            }
            psA += __shfl_xor_sync(0xffffffffu, psA, 1);
            psB += __shfl_xor_sync(0xffffffffu, psB, 1);
            psA += __shfl_xor_sync(0xffffffffu, psA, 2);
            psB += __shfl_xor_sync(0xffffffffu, psB, 2);
            lA[mt] = lA[mt] * scA + psA;
            lB[mt] = lB[mt] * scB + psB;

            #pragma unroll
            for (int nt = 0; nt < 8; nt++) {
                Oc[mt][nt][0] *= scA; Oc[mt][nt][1] *= scA;
                Oc[mt][nt][2] *= scB; Oc[mt][nt][3] *= scB;
            }
        }

        // O += P @ V : P A-fragments built from Sc D-fragments by shuffle.
        // k-step ks of PV = n-block ks of S (cols ks*8..ks*8+7).
        #pragma unroll
        for (int ks = 0; ks < 8; ks++) {
            unsigned pa[2][4];
            #pragma unroll
            for (int mt = 0; mt < 2; mt++) {
                float p0 = Sc[mt][ks][0], p1 = Sc[mt][ks][1];
                float p2 = Sc[mt][ks][2], p3 = Sc[mt][ks][3];
                float x0 = __shfl_sync(0xffffffffu, p0, srcA);
                float x1 = __shfl_sync(0xffffffffu, p1, srcA);
                float x2 = __shfl_sync(0xffffffffu, p2, srcA);
                float x3 = __shfl_sync(0xffffffffu, p3, srcA);
                float y0 = __shfl_sync(0xffffffffu, p0, srcB);
                float y1 = __shfl_sync(0xffffffffu, p1, srcB);
                float y2 = __shfl_sync(0xffffffffu, p2, srcB);
                float y3 = __shfl_sync(0xffffffffu, p3, srcB);
                pa[mt][0] = f2tf(odd ? x1 : x0);
                pa[mt][1] = f2tf(odd ? x3 : x2);
                pa[mt][2] = f2tf(odd ? y1 : y0);
                pa[mt][3] = f2tf(odd ? y3 : y2);
            }
            #pragma unroll
            for (int nt = 0; nt < 8; nt++) {
                unsigned bb[2];
                const float* vp = &Vsb[(ks * 8 + t) * VS_ST + nt * 8 + g];
                bb[0] = f2tf(vp[0]);
                bb[1] = f2tf(vp[4 * VS_ST]);
                mma8(Oc[0][nt], pa[0], bb);
                mma8(Oc[1][nt], pa[1], bb);
            }
        }
        __syncthreads();   // before next tile's cp.async overwrites this buffer
    }

    // Epilogue: normalize, write (B,L,D)
    #pragma unroll
    for (int mt = 0; mt < 2; mt++) {
        float iA = 1.f / lA[mt], iB = 1.f / lB[mt];
        int rowA = q0 + w * 32 + mt * 16 + g;
        size_t baseA = ((size_t)b * NL + rowA) * ND + h * NDK;
        size_t baseB = baseA + (size_t)8 * ND;
        #pragma unroll
        for (int nt = 0; nt < 8; nt++) {
            int cb = nt * 8 + 2 * t;
            *(float2*)&g_att[baseA + cb] =
                make_float2(Oc[mt][nt][0] * iA, Oc[mt][nt][1] * iA);
            *(float2*)&g_att[baseB + cb] =
                make_float2(Oc[mt][nt][2] * iB, Oc[mt][nt][3] * iB);
        }
    }
}

// ---------------------------------------------------------------------------
extern "C" void kernel_launch(void* const* d_in, const int* in_sizes, int n_in,
                              void* d_out, int out_size)
{
    (void)in_sizes; (void)n_in; (void)out_size;
    const float* x  = (const float*)d_in[0];
    const float* Wq = (const float*)d_in[1];
    const float* Wk = (const float*)d_in[2];
    const float* Wv = (const float*)d_in[3];
    const float* Wo = (const float*)d_in[4];
    const float* wf = (const float*)d_in[5];
    const float* wp = (const float*)d_in[6];
    float* out = (float*)d_out;

    float *Qp, *Kp, *Vp, *Ap;
    cudaGetSymbolAddress((void**)&Qp, g_Q);
    cudaGetSymbolAddress((void**)&Kp, g_K);
    cudaGetSymbolAddress((void**)&Vp, g_V);
    cudaGetSymbolAddress((void**)&Ap, g_att);

    cudaFuncSetAttribute(gemm_qkv, cudaFuncAttributeMaxDynamicSharedMemorySize, SMEM_GEMM4);
    cudaFuncSetAttribute(gemm_out, cudaFuncAttributeMaxDynamicSharedMemorySize, SMEM_GEMM2);
    cudaFuncSetAttribute(wave_attn_tc, cudaFuncAttributeMaxDynamicSharedMemorySize, SMEM_ATTN);

    dim3 ggrid(8, 32, 3);   // (N/64, M/256, qkv)
    gemm_qkv<<<ggrid, 256, SMEM_GEMM4>>>(x, Wq, Wk, Wv, Qp, Kp, Vp);

    wave_attn_tc<<<dim3(16, 32), 128, SMEM_ATTN>>>(wf, wp);

    gemm_out<<<dim3(8, 64), 256, SMEM_GEMM2>>>(Ap, Wo, out);
}